// round 15
// baseline (speedup 1.0000x reference)
#include <cuda_runtime.h>
#include <cuda_bf16.h>
#include <stdint.h>
#include <math.h>

#define NTOKEN 50257
#define NROWS  2240
#define DIM    400
#define KPAD   448              // 7 * 64
#define MPAD   2304             // 18 * 128
#define NPAD   50304            // 393 * 128
#define KTILES 7                // k-chunks of 64
#define NTILES (NPAD / 128)     // 393 col-tiles
#define SROW   144              // bytes per smem row (128 data + 16 pad) -> conflict-free
#define TILE_B (128 * SROW)     // 18432
#define STAGE_BYTES (2 * TILE_B)          // A+B = 36864
#define SMEM_DYN (2 * STAGE_BYTES)        // 73728 (also >= 128*132*4 = 67584 staging)
#define OSTRIDE 132             // fp32 staging stride

#define XGRP ((long long)MPAD * (KPAD / 8))
#define WGRP ((long long)NPAD * (KPAD / 8))
#define WBLK ((int)((WGRP + 255) / 256))

// ---------------- device scratch ----------------
__device__ int   g_last[NTOKEN];
__device__ float g_sfac[NROWS];
__device__ float g_noise[NROWS];
__device__ float g_pm[(size_t)NROWS * NTILES];
__device__ float g_ps[(size_t)NROWS * NTILES];
__device__ __nv_bfloat16 g_xa[(size_t)MPAD * KPAD];
__device__ __nv_bfloat16 g_wb[(size_t)NPAD * KPAD];

// ---------------- helpers ----------------
__device__ __forceinline__ uint32_t smem_u32(const void* p) {
    uint32_t a;
    asm("{ .reg .u64 t; cvta.to.shared.u64 t, %1; cvt.u32.u64 %0, t; }" : "=r"(a) : "l"(p));
    return a;
}
__device__ __forceinline__ void ldsm_x4(uint32_t& r0, uint32_t& r1, uint32_t& r2, uint32_t& r3,
                                        uint32_t addr) {
    asm volatile("ldmatrix.sync.aligned.m8n8.x4.shared.b16 {%0,%1,%2,%3}, [%4];"
                 : "=r"(r0), "=r"(r1), "=r"(r2), "=r"(r3) : "r"(addr));
}
__device__ __forceinline__ void mma16816(float* c, uint32_t a0, uint32_t a1, uint32_t a2,
                                         uint32_t a3, uint32_t b0, uint32_t b1) {
    asm volatile("mma.sync.aligned.m16n8k16.row.col.f32.bf16.bf16.f32 "
                 "{%0,%1,%2,%3}, {%4,%5,%6,%7}, {%8,%9}, {%0,%1,%2,%3};"
                 : "+f"(c[0]), "+f"(c[1]), "+f"(c[2]), "+f"(c[3])
                 : "r"(a0), "r"(a1), "r"(a2), "r"(a3), "r"(b0), "r"(b1));
}
__device__ __forceinline__ void cp16(uint32_t dst, const void* src) {
    asm volatile("cp.async.cg.shared.global [%0], [%1], 16;" :: "r"(dst), "l"(src));
}
#define CP_COMMIT() asm volatile("cp.async.commit_group;" ::: "memory")
#define CP_WAIT0()  asm volatile("cp.async.wait_group 0;" ::: "memory")

__device__ __forceinline__ float warp_sum(float v) {
    #pragma unroll
    for (int o = 16; o; o >>= 1) v += __shfl_down_sync(0xffffffffu, v, o);
    return v;
}

// ---------------- fp32 -> padded bf16 conversion body ----------------
__device__ __forceinline__ void cvt_one(const float* __restrict__ src,
                                        __nv_bfloat16* __restrict__ dst,
                                        int srows, long long i) {
    int row = (int)(i / (KPAD / 8));
    int g   = (int)(i % (KPAD / 8));
    __align__(16) __nv_bfloat16 v[8];
    if (row < srows && g * 8 < DIM) {
        const float* s = src + (long long)row * DIM + g * 8;
        #pragma unroll
        for (int j = 0; j < 8; j++) v[j] = __float2bfloat16(s[j]);
    } else {
        #pragma unroll
        for (int j = 0; j < 8; j++) v[j] = __float2bfloat16(0.f);
    }
    *reinterpret_cast<uint4*>(dst + (size_t)row * KPAD + g * 8) =
        *reinterpret_cast<const uint4*>(v);
}

// ---------------- launch 1: cvt_x + init_last ----------------
__global__ void k_pro_a(const float* __restrict__ x, const int* __restrict__ tgt) {
    long long i = (long long)blockIdx.x * blockDim.x + threadIdx.x;
    if (i < NROWS) g_last[tgt[i]] = -1;
    if (i < XGRP) cvt_one(x, g_xa, NROWS, i);
}

// ---------------- launch 2: cvt_w + row_stats (block-partitioned) ----------------
__global__ void k_pro_b(const float* __restrict__ dec_w,
                        const float* __restrict__ x,
                        const float* __restrict__ enc_w,
                        const int* __restrict__ tgt) {
    if (blockIdx.x < WBLK) {
        long long i = (long long)blockIdx.x * blockDim.x + threadIdx.x;
        if (i < WGRP) cvt_one(dec_w, g_wb, NTOKEN, i);
        return;
    }
    int row = blockIdx.x - WBLK;
    int t = tgt[row];
    const float* hr = x + (long long)row * DIM;
    const float* wr = enc_w + (long long)t * DIM;
    float hsq = 0.f, dhw = 0.f, wsq = 0.f;
    for (int k = threadIdx.x; k < DIM; k += blockDim.x) {
        float hv = hr[k], wv = wr[k];
        hsq += hv * hv; dhw += hv * wv; wsq += wv * wv;
    }
    __shared__ float sh[3][8];
    int lane = threadIdx.x & 31, w = threadIdx.x >> 5;
    hsq = warp_sum(hsq); dhw = warp_sum(dhw); wsq = warp_sum(wsq);
    if (lane == 0) { sh[0][w] = hsq; sh[1][w] = dhw; sh[2][w] = wsq; }
    __syncthreads();
    if (threadIdx.x == 0) {
        hsq = 0.f; dhw = 0.f; wsq = 0.f;
        #pragma unroll
        for (int i = 0; i < 8; i++) { hsq += sh[0][i]; dhw += sh[1][i]; wsq += sh[2][i]; }
        float n_out = sqrtf(hsq + 1e-8f);
        float n_w   = sqrtf(wsq + 1e-8f);
        float cosv  = dhw / (n_out * n_w);
        float eps   = (cosv > 0.f) ? 0.2f * n_w : 0.f;
        g_sfac[row] = -eps / n_out;
        atomicMax(&g_last[t], row);
    }
}

// ---------------- launch 3: noise dot products ----------------
__global__ void k_noise(const float* __restrict__ h, const int* __restrict__ tgt) {
    int row = blockIdx.x;
    int j = g_last[tgt[row]];
    const float* hi = h + (long long)row * DIM;
    const float* hj = h + (long long)j * DIM;
    float d = 0.f;
    for (int k = threadIdx.x; k < DIM; k += blockDim.x) d += hi[k] * hj[k];
    __shared__ float sh[4];
    d = warp_sum(d);
    if ((threadIdx.x & 31) == 0) sh[threadIdx.x >> 5] = d;
    __syncthreads();
    if (threadIdx.x == 0)
        g_noise[row] = g_sfac[j] * (sh[0] + sh[1] + sh[2] + sh[3]);
}

// ---------------- launch 4: HMMA bf16 GEMM, 64x64 warp tiles (4 warps) ----------------
// 128x128 CTA tile, 128 threads, 2 CTAs/SM. Warp grid 2M x 2N ->
// smem LDSM duplication A x2, B x2 (was A x2, B x4).
__global__ void __launch_bounds__(128, 2) k_gemm_tc(
    const float* __restrict__ bias, const int* __restrict__ tgt,
    float* __restrict__ out)
{
    extern __shared__ __align__(16) char dyn[];
    __shared__ int   s_tgt[128];
    __shared__ float s_noise[128];
    __shared__ float s_bias[128];
    __shared__ float sm_m[2][128];
    __shared__ float sm_s[2][128];

    int tid = threadIdx.x, lane = tid & 31, wid = tid >> 5;
    int warpM = wid & 1, warpN = wid >> 1;
    int rowBase = blockIdx.y * 128, colBase = blockIdx.x * 128;

    {
        int gr = rowBase + tid;
        s_tgt[tid]   = (gr < NROWS) ? tgt[gr]     : -1;
        s_noise[tid] = (gr < NROWS) ? g_noise[gr] : 0.f;
        int gc = colBase + tid;
        s_bias[tid]  = (gc < NTOKEN) ? bias[gc]   : 0.f;
    }

    // copy mapping: per matrix tile 1024 16B chunks, 8/thread.
    // chunk i: row = (tid>>3) + i*16, col-chunk = tid&7  (immediate offsets)
    uint32_t dynBase = smem_u32(dyn);
    int r0 = tid >> 3, c0 = tid & 7;
    const __nv_bfloat16* gA0 = &g_xa[(size_t)(rowBase + r0) * KPAD + c0 * 8];
    const __nv_bfloat16* gB0 = &g_wb[(size_t)(colBase + r0) * KPAD + c0 * 8];
    uint32_t dA0 = dynBase + (uint32_t)(r0 * SROW + c0 * 16);
    uint32_t dB0 = dynBase + TILE_B + (uint32_t)(r0 * SROW + c0 * 16);

    // hoisted ldmatrix addresses
    uint32_t aOff[4], bOff[4];
    #pragma unroll
    for (int mf = 0; mf < 4; mf++) {
        int row = warpM * 64 + mf * 16 + (lane & 7) + ((lane >> 3) & 1) * 8;
        aOff[mf] = dynBase + (uint32_t)(row * SROW + ((lane >> 4) & 1) * 16);
    }
    #pragma unroll
    for (int nf2 = 0; nf2 < 4; nf2++) {
        int rn = warpN * 64 + nf2 * 16 + (lane & 7) + ((lane >> 4) & 1) * 8;
        bOff[nf2] = dynBase + (uint32_t)(TILE_B + rn * SROW + ((lane >> 3) & 1) * 16);
    }

    float acc[4][8][4];
    #pragma unroll
    for (int m = 0; m < 4; m++)
        #pragma unroll
        for (int n = 0; n < 8; n++)
            #pragma unroll
            for (int j = 0; j < 4; j++) acc[m][n][j] = 0.f;

    // preload k-tile 0 into stage 0
    #pragma unroll
    for (int i = 0; i < 8; i++) {
        cp16(dA0 + i * (16 * SROW), gA0 + (size_t)i * 16 * KPAD);
        cp16(dB0 + i * (16 * SROW), gB0 + (size_t)i * 16 * KPAD);
    }
    CP_COMMIT();

    for (int kt = 0; kt < KTILES; kt++) {
        uint32_t stBase = (kt & 1) * (uint32_t)STAGE_BYTES;
        CP_WAIT0();
        __syncthreads();
        if (kt + 1 < KTILES) {
            uint32_t nb = ((kt + 1) & 1) * (uint32_t)STAGE_BYTES;
            int k0 = (kt + 1) * 64;
            #pragma unroll
            for (int i = 0; i < 8; i++) {
                cp16(dA0 + nb + i * (16 * SROW), gA0 + k0 + (size_t)i * 16 * KPAD);
                cp16(dB0 + nb + i * (16 * SROW), gB0 + k0 + (size_t)i * 16 * KPAD);
            }
            CP_COMMIT();
        }
        #pragma unroll
        for (int s = 0; s < 4; s++) {
            uint32_t sOff = stBase + s * 32;
            uint32_t a[4][4];
            #pragma unroll
            for (int mf = 0; mf < 4; mf++)
                ldsm_x4(a[mf][0], a[mf][1], a[mf][2], a[mf][3], sOff + aOff[mf]);
            uint32_t b[8][2];
            #pragma unroll
            for (int nf2 = 0; nf2 < 4; nf2++)
                ldsm_x4(b[nf2 * 2][0], b[nf2 * 2][1], b[nf2 * 2 + 1][0], b[nf2 * 2 + 1][1],
                        sOff + bOff[nf2]);
            #pragma unroll
            for (int mf = 0; mf < 4; mf++)
                #pragma unroll
                for (int nf = 0; nf < 8; nf++)
                    mma16816(acc[mf][nf], a[mf][0], a[mf][1], a[mf][2], a[mf][3],
                             b[nf][0], b[nf][1]);
        }
    }
    __syncthreads();   // mainloop done; dyn[] reusable for fp32 staging

    // Phase 1: bias + target-noise + partial (max,sumexp); stage values in smem.
    float* stage = reinterpret_cast<float*>(dyn);
    int groupRow = lane >> 2;
    int colPair  = (lane & 3) * 2;
    #pragma unroll
    for (int mf = 0; mf < 4; mf++) {
        #pragma unroll
        for (int half = 0; half < 2; half++) {
            int rl = warpM * 64 + mf * 16 + groupRow + half * 8;
            int gr = rowBase + rl;
            if (gr >= NROWS) continue;           // warp-uniform (8-row granularity)
            int t = s_tgt[rl];
            float nz = s_noise[rl];
            float vv[16];
            float lm = -1e30f;
            #pragma unroll
            for (int nf = 0; nf < 8; nf++) {
                int cl = warpN * 64 + nf * 8 + colPair;
                int gc = colBase + cl;
                float v0 = acc[mf][nf][half * 2 + 0] + s_bias[cl];
                float v1 = acc[mf][nf][half * 2 + 1] + s_bias[cl + 1];
                if (gc == t)     v0 += nz;
                if (gc + 1 == t) v1 += nz;
                *reinterpret_cast<float2*>(&stage[rl * OSTRIDE + cl]) = make_float2(v0, v1);
                vv[nf * 2]     = (gc < NTOKEN)     ? v0 : -1e30f;
                vv[nf * 2 + 1] = (gc + 1 < NTOKEN) ? v1 : -1e30f;
                lm = fmaxf(lm, fmaxf(vv[nf * 2], vv[nf * 2 + 1]));
            }
            float ls = 0.f;
            #pragma unroll
            for (int q = 0; q < 16; q++) ls += __expf(vv[q] - lm);
            #pragma unroll
            for (int o = 1; o <= 2; o <<= 1) {
                float om = __shfl_xor_sync(0xffffffffu, lm, o);
                float os = __shfl_xor_sync(0xffffffffu, ls, o);
                float nm = fmaxf(lm, om);
                ls = ls * __expf(lm - nm) + os * __expf(om - nm);
                lm = nm;
            }
            if ((lane & 3) == 0) { sm_m[warpN][rl] = lm; sm_s[warpN][rl] = ls; }
        }
    }
    __syncthreads();

    // Phase 2: coalesced row-contiguous stores (warp = 32 rows, 32 lanes = 32 cols).
    bool colFull = (colBase + 128 <= NTOKEN);
    #pragma unroll 1
    for (int rr = 0; rr < 32; rr++) {
        int rl = wid * 32 + rr;
        int gr = rowBase + rl;
        if (gr >= NROWS) continue;               // warp-uniform
        size_t ob = (size_t)gr * NTOKEN + colBase;
        const float* srow = &stage[rl * OSTRIDE];
        if (colFull) {
            #pragma unroll
            for (int q = 0; q < 4; q++)
                out[ob + lane + q * 32] = srow[lane + q * 32];
        } else {
            #pragma unroll
            for (int q = 0; q < 4; q++) {
                int c = lane + q * 32;
                if (colBase + c < NTOKEN) out[ob + c] = srow[c];
            }
        }
    }

    // partial (m,s) combine + write
    {
        int gr = rowBase + tid;
        if (gr < NROWS) {
            float m0 = sm_m[0][tid], s0 = sm_s[0][tid];
            float m1 = sm_m[1][tid], s1 = sm_s[1][tid];
            float mm = fmaxf(m0, m1);
            float ssum = s0 * __expf(m0 - mm) + s1 * __expf(m1 - mm);
            g_pm[(size_t)gr * NTILES + blockIdx.x] = mm;
            g_ps[(size_t)gr * NTILES + blockIdx.x] = ssum;
        }
    }
}

// ---------------- launch 5: finalize lse + subtract (fused) ----------------
__global__ void k_subfin(float* __restrict__ out) {
    int row = blockIdx.x;
    const float* pm = &g_pm[(size_t)row * NTILES];
    const float* ps = &g_ps[(size_t)row * NTILES];
    float m = -1e30f, s = 0.f;
    for (int i = threadIdx.x; i < NTILES; i += blockDim.x) {
        float tm = pm[i], ts = ps[i];
        float nm = fmaxf(m, tm);
        s = s * __expf(m - nm) + ts * __expf(tm - nm);
        m = nm;
    }
    int lane = threadIdx.x & 31, w = threadIdx.x >> 5;
    #pragma unroll
    for (int o = 16; o; o >>= 1) {
        float om = __shfl_xor_sync(0xffffffffu, m, o);
        float os = __shfl_xor_sync(0xffffffffu, s, o);
        float nm = fmaxf(m, om);
        s = s * __expf(m - nm) + os * __expf(om - nm);
        m = nm;
    }
    __shared__ float shm[32], shs[32];
    __shared__ float sh_l;
    if (lane == 0) { shm[w] = m; shs[w] = s; }
    __syncthreads();
    if (threadIdx.x == 0) {
        int nw = (int)(blockDim.x >> 5);
        m = shm[0]; s = shs[0];
        for (int i = 1; i < nw; i++) {
            float nm = fmaxf(m, shm[i]);
            s = s * __expf(m - nm) + shs[i] * __expf(shm[i] - nm);
            m = nm;
        }
        sh_l = m + __logf(s);
    }
    __syncthreads();
    float l = sh_l;

    float* p = out + (size_t)row * NTOKEN;
    int head = (int)(((16u - ((uint32_t)(uintptr_t)p & 15u)) & 15u) >> 2);
    int n4 = (NTOKEN - head) >> 2;
    int tail = NTOKEN - head - n4 * 4;
    if (threadIdx.x < (unsigned)head) p[threadIdx.x] -= l;
    float4* p4 = (float4*)(p + head);
    for (int i = threadIdx.x; i < n4; i += blockDim.x) {
        float4 v = p4[i];
        v.x -= l; v.y -= l; v.z -= l; v.w -= l;
        p4[i] = v;
    }
    if (threadIdx.x < (unsigned)tail) p[head + n4 * 4 + threadIdx.x] -= l;
}

// ---------------- launch ----------------
extern "C" void kernel_launch(void* const* d_in, const int* in_sizes, int n_in,
                              void* d_out, int out_size) {
    const float* x     = (const float*)d_in[0];
    const float* dec_w = (const float*)d_in[1];
    const float* dec_b = (const float*)d_in[2];
    const float* enc_w = (const float*)d_in[3];
    const int*   tgt   = (const int*)d_in[4];
    float* out = (float*)d_out;

    k_pro_a<<<(unsigned)((XGRP + 255) / 256), 256>>>(x, tgt);            // 1
    k_pro_b<<<(unsigned)(WBLK + NROWS), 256>>>(dec_w, x, enc_w, tgt);    // 2
    k_noise<<<NROWS, 128>>>(x, tgt);                                     // 3
    cudaFuncSetAttribute(k_gemm_tc, cudaFuncAttributeMaxDynamicSharedMemorySize, SMEM_DYN);
    dim3 grid(NPAD / 128, MPAD / 128);
    k_gemm_tc<<<grid, 128, SMEM_DYN>>>(dec_b, tgt, out);                 // 4 (profiled)
    k_subfin<<<NROWS, 1024>>>(out);                                      // 5
}

// round 16
// speedup vs baseline: 1.1285x; 1.1285x over previous
#include <cuda_runtime.h>
#include <cuda_bf16.h>
#include <stdint.h>
#include <math.h>

#define NTOKEN 50257
#define NROWS  2240
#define DIM    400
#define KPAD   448              // 7 * 64
#define MPAD   2304             // 18 * 128
#define NPAD   50304            // 393 * 128
#define KTILES 7                // k-chunks of 64
#define NTILES (NPAD / 128)     // 393 col-tiles
#define SROW   144              // bytes per smem row (128 data + 16 pad) -> conflict-free
#define TILE_B (128 * SROW)     // 18432
#define STAGE_BYTES (2 * TILE_B)          // A+B = 36864
#define NSTAGE 3
#define SMEM_DYN (NSTAGE * STAGE_BYTES)   // 110592 (>= 128*132*4 staging)
#define OSTRIDE 132             // fp32 staging stride

#define XGRP ((long long)MPAD * (KPAD / 8))
#define WGRP ((long long)NPAD * (KPAD / 8))
#define WBLK ((int)((WGRP + 255) / 256))

// ---------------- device scratch ----------------
__device__ int   g_last[NTOKEN];
__device__ float g_sfac[NROWS];
__device__ float g_noise[NROWS];
__device__ float g_pm[(size_t)NROWS * NTILES];
__device__ float g_ps[(size_t)NROWS * NTILES];
__device__ __nv_bfloat16 g_xa[(size_t)MPAD * KPAD];
__device__ __nv_bfloat16 g_wb[(size_t)NPAD * KPAD];

// ---------------- helpers ----------------
__device__ __forceinline__ uint32_t smem_u32(const void* p) {
    uint32_t a;
    asm("{ .reg .u64 t; cvta.to.shared.u64 t, %1; cvt.u32.u64 %0, t; }" : "=r"(a) : "l"(p));
    return a;
}
__device__ __forceinline__ void ldsm_x4(uint32_t& r0, uint32_t& r1, uint32_t& r2, uint32_t& r3,
                                        uint32_t addr) {
    asm volatile("ldmatrix.sync.aligned.m8n8.x4.shared.b16 {%0,%1,%2,%3}, [%4];"
                 : "=r"(r0), "=r"(r1), "=r"(r2), "=r"(r3) : "r"(addr));
}
__device__ __forceinline__ void mma16816(float* c, uint32_t a0, uint32_t a1, uint32_t a2,
                                         uint32_t a3, uint32_t b0, uint32_t b1) {
    asm volatile("mma.sync.aligned.m16n8k16.row.col.f32.bf16.bf16.f32 "
                 "{%0,%1,%2,%3}, {%4,%5,%6,%7}, {%8,%9}, {%0,%1,%2,%3};"
                 : "+f"(c[0]), "+f"(c[1]), "+f"(c[2]), "+f"(c[3])
                 : "r"(a0), "r"(a1), "r"(a2), "r"(a3), "r"(b0), "r"(b1));
}
__device__ __forceinline__ void cp16(uint32_t dst, const void* src) {
    asm volatile("cp.async.cg.shared.global [%0], [%1], 16;" :: "r"(dst), "l"(src));
}
#define CP_COMMIT() asm volatile("cp.async.commit_group;" ::: "memory")
#define CP_WAIT0()  asm volatile("cp.async.wait_group 0;" ::: "memory")
#define CP_WAIT1()  asm volatile("cp.async.wait_group 1;" ::: "memory")

__device__ __forceinline__ float warp_sum(float v) {
    #pragma unroll
    for (int o = 16; o; o >>= 1) v += __shfl_down_sync(0xffffffffu, v, o);
    return v;
}

// ---------------- fp32 -> padded bf16 conversion body ----------------
__device__ __forceinline__ void cvt_one(const float* __restrict__ src,
                                        __nv_bfloat16* __restrict__ dst,
                                        int srows, long long i) {
    int row = (int)(i / (KPAD / 8));
    int g   = (int)(i % (KPAD / 8));
    __align__(16) __nv_bfloat16 v[8];
    if (row < srows && g * 8 < DIM) {
        const float* s = src + (long long)row * DIM + g * 8;
        #pragma unroll
        for (int j = 0; j < 8; j++) v[j] = __float2bfloat16(s[j]);
    } else {
        #pragma unroll
        for (int j = 0; j < 8; j++) v[j] = __float2bfloat16(0.f);
    }
    *reinterpret_cast<uint4*>(dst + (size_t)row * KPAD + g * 8) =
        *reinterpret_cast<const uint4*>(v);
}

// ---------------- launch 1: cvt_x + init_last ----------------
__global__ void k_pro_a(const float* __restrict__ x, const int* __restrict__ tgt) {
    long long i = (long long)blockIdx.x * blockDim.x + threadIdx.x;
    if (i < NROWS) g_last[tgt[i]] = -1;
    if (i < XGRP) cvt_one(x, g_xa, NROWS, i);
}

// ---------------- launch 2: cvt_w + row_stats (block-partitioned) ----------------
__global__ void k_pro_b(const float* __restrict__ dec_w,
                        const float* __restrict__ x,
                        const float* __restrict__ enc_w,
                        const int* __restrict__ tgt) {
    if (blockIdx.x < WBLK) {
        long long i = (long long)blockIdx.x * blockDim.x + threadIdx.x;
        if (i < WGRP) cvt_one(dec_w, g_wb, NTOKEN, i);
        return;
    }
    int row = blockIdx.x - WBLK;
    int t = tgt[row];
    const float* hr = x + (long long)row * DIM;
    const float* wr = enc_w + (long long)t * DIM;
    float hsq = 0.f, dhw = 0.f, wsq = 0.f;
    for (int k = threadIdx.x; k < DIM; k += blockDim.x) {
        float hv = hr[k], wv = wr[k];
        hsq += hv * hv; dhw += hv * wv; wsq += wv * wv;
    }
    __shared__ float sh[3][8];
    int lane = threadIdx.x & 31, w = threadIdx.x >> 5;
    hsq = warp_sum(hsq); dhw = warp_sum(dhw); wsq = warp_sum(wsq);
    if (lane == 0) { sh[0][w] = hsq; sh[1][w] = dhw; sh[2][w] = wsq; }
    __syncthreads();
    if (threadIdx.x == 0) {
        hsq = 0.f; dhw = 0.f; wsq = 0.f;
        #pragma unroll
        for (int i = 0; i < 8; i++) { hsq += sh[0][i]; dhw += sh[1][i]; wsq += sh[2][i]; }
        float n_out = sqrtf(hsq + 1e-8f);
        float n_w   = sqrtf(wsq + 1e-8f);
        float cosv  = dhw / (n_out * n_w);
        float eps   = (cosv > 0.f) ? 0.2f * n_w : 0.f;
        g_sfac[row] = -eps / n_out;
        atomicMax(&g_last[t], row);
    }
}

// ---------------- launch 3: noise dot products ----------------
__global__ void k_noise(const float* __restrict__ h, const int* __restrict__ tgt) {
    int row = blockIdx.x;
    int j = g_last[tgt[row]];
    const float* hi = h + (long long)row * DIM;
    const float* hj = h + (long long)j * DIM;
    float d = 0.f;
    for (int k = threadIdx.x; k < DIM; k += blockDim.x) d += hi[k] * hj[k];
    __shared__ float sh[4];
    d = warp_sum(d);
    if ((threadIdx.x & 31) == 0) sh[threadIdx.x >> 5] = d;
    __syncthreads();
    if (threadIdx.x == 0)
        g_noise[row] = g_sfac[j] * (sh[0] + sh[1] + sh[2] + sh[3]);
}

// ---------------- launch 4: HMMA bf16 GEMM, k64 chunks, 3-stage cp.async ----------------
// R14 base; only change: 3-stage ring + wait_group 1 so the awaited group
// was issued two compute-chunks ago (covers DRAM/L2 latency fully).
__global__ void __launch_bounds__(256, 2) k_gemm_tc(
    const float* __restrict__ bias, const int* __restrict__ tgt,
    float* __restrict__ out)
{
    extern __shared__ __align__(16) char dyn[];
    __shared__ int   s_tgt[128];
    __shared__ float s_noise[128];
    __shared__ float s_bias[128];
    __shared__ float sm_m[2][128];
    __shared__ float sm_s[2][128];

    int tid = threadIdx.x, lane = tid & 31, wid = tid >> 5;
    int warpM = wid & 3, warpN = wid >> 2;
    int rowBase = blockIdx.y * 128, colBase = blockIdx.x * 128;

    if (tid < 128) {
        int gr = rowBase + tid;
        s_tgt[tid]   = (gr < NROWS) ? tgt[gr]     : -1;
        s_noise[tid] = (gr < NROWS) ? g_noise[gr] : 0.f;
        int gc = colBase + tid;
        s_bias[tid]  = (gc < NTOKEN) ? bias[gc]   : 0.f;
    }

    uint32_t dynBase = smem_u32(dyn);
    const __nv_bfloat16* gA[4];
    const __nv_bfloat16* gB[4];
    uint32_t dA[4], dB[4];
    #pragma unroll
    for (int i = 0; i < 4; i++) {
        int idx = tid + i * 256;
        int r = idx >> 3, c = idx & 7;
        gA[i] = &g_xa[(size_t)(rowBase + r) * KPAD + c * 8];
        gB[i] = &g_wb[(size_t)(colBase + r) * KPAD + c * 8];
        dA[i] = dynBase + (uint32_t)(r * SROW + c * 16);
        dB[i] = dynBase + TILE_B + (uint32_t)(r * SROW + c * 16);
    }

    uint32_t aOff[2], bOff[4];
    #pragma unroll
    for (int mf = 0; mf < 2; mf++) {
        int row = warpM * 32 + mf * 16 + (lane & 7) + ((lane >> 3) & 1) * 8;
        aOff[mf] = dynBase + (uint32_t)(row * SROW + ((lane >> 4) & 1) * 16);
    }
    #pragma unroll
    for (int nf2 = 0; nf2 < 4; nf2++) {
        int rn = warpN * 64 + nf2 * 16 + (lane & 7) + ((lane >> 4) & 1) * 8;
        bOff[nf2] = dynBase + (uint32_t)(TILE_B + rn * SROW + ((lane >> 3) & 1) * 16);
    }

    float acc[2][8][4];
    #pragma unroll
    for (int m = 0; m < 2; m++)
        #pragma unroll
        for (int n = 0; n < 8; n++)
            #pragma unroll
            for (int j = 0; j < 4; j++) acc[m][n][j] = 0.f;

    // prologue: issue chunks 0 and 1 into stages 0 and 1
    #pragma unroll
    for (int p = 0; p < 2; p++) {
        uint32_t so = p * (uint32_t)STAGE_BYTES;
        int k0 = p * 64;
        #pragma unroll
        for (int i = 0; i < 4; i++) {
            cp16(dA[i] + so, gA[i] + k0);
            cp16(dB[i] + so, gB[i] + k0);
        }
        CP_COMMIT();
    }

    int st = 0;            // stage of chunk kt
    for (int kt = 0; kt < KTILES; kt++) {
        if (kt + 1 < KTILES) CP_WAIT1(); else CP_WAIT0();
        __syncthreads();   // all warps done with stage (kt+2)%3 (consumed at kt-1)
        if (kt + 2 < KTILES) {
            int st2 = st + 2; if (st2 >= NSTAGE) st2 -= NSTAGE;
            uint32_t nb = st2 * (uint32_t)STAGE_BYTES;
            int k0 = (kt + 2) * 64;
            #pragma unroll
            for (int i = 0; i < 4; i++) {
                cp16(dA[i] + nb, gA[i] + k0);
                cp16(dB[i] + nb, gB[i] + k0);
            }
            CP_COMMIT();
        }
        uint32_t stBase = st * (uint32_t)STAGE_BYTES;
        #pragma unroll
        for (int s = 0; s < 4; s++) {
            uint32_t sOff = stBase + s * 32;
            uint32_t a[2][4];
            #pragma unroll
            for (int mf = 0; mf < 2; mf++)
                ldsm_x4(a[mf][0], a[mf][1], a[mf][2], a[mf][3], sOff + aOff[mf]);
            uint32_t b[8][2];
            #pragma unroll
            for (int nf2 = 0; nf2 < 4; nf2++)
                ldsm_x4(b[nf2 * 2][0], b[nf2 * 2][1], b[nf2 * 2 + 1][0], b[nf2 * 2 + 1][1],
                        sOff + bOff[nf2]);
            #pragma unroll
            for (int mf = 0; mf < 2; mf++)
                #pragma unroll
                for (int nf = 0; nf < 8; nf++)
                    mma16816(acc[mf][nf], a[mf][0], a[mf][1], a[mf][2], a[mf][3],
                             b[nf][0], b[nf][1]);
        }
        if (++st == NSTAGE) st = 0;
    }
    __syncthreads();   // mainloop done; dyn[] buffers now reusable for staging

    // Phase 1: bias + target-noise + partial (max,sumexp); stage values in smem.
    float* stage = reinterpret_cast<float*>(dyn);
    int groupRow = lane >> 2;
    int colPair  = (lane & 3) * 2;
    #pragma unroll
    for (int mf = 0; mf < 2; mf++) {
        #pragma unroll
        for (int half = 0; half < 2; half++) {
            int rl = warpM * 32 + mf * 16 + groupRow + half * 8;
            int gr = rowBase + rl;
            if (gr >= NROWS) continue;           // warp-uniform (NROWS % 32 == 0)
            int t = s_tgt[rl];
            float nz = s_noise[rl];
            float vv[16];
            float lm = -1e30f;
            #pragma unroll
            for (int nf = 0; nf < 8; nf++) {
                int cl = warpN * 64 + nf * 8 + colPair;
                int gc = colBase + cl;
                float v0 = acc[mf][nf][half * 2 + 0] + s_bias[cl];
                float v1 = acc[mf][nf][half * 2 + 1] + s_bias[cl + 1];
                if (gc == t)     v0 += nz;
                if (gc + 1 == t) v1 += nz;
                *reinterpret_cast<float2*>(&stage[rl * OSTRIDE + cl]) = make_float2(v0, v1);
                vv[nf * 2]     = (gc < NTOKEN)     ? v0 : -1e30f;
                vv[nf * 2 + 1] = (gc + 1 < NTOKEN) ? v1 : -1e30f;
                lm = fmaxf(lm, fmaxf(vv[nf * 2], vv[nf * 2 + 1]));
            }
            float ls = 0.f;
            #pragma unroll
            for (int q = 0; q < 16; q++) ls += __expf(vv[q] - lm);
            #pragma unroll
            for (int o = 1; o <= 2; o <<= 1) {
                float om = __shfl_xor_sync(0xffffffffu, lm, o);
                float os = __shfl_xor_sync(0xffffffffu, ls, o);
                float nm = fmaxf(lm, om);
                ls = ls * __expf(lm - nm) + os * __expf(om - nm);
                lm = nm;
            }
            if ((lane & 3) == 0) { sm_m[warpN][rl] = lm; sm_s[warpN][rl] = ls; }
        }
    }
    __syncthreads();

    // Phase 2: coalesced row-contiguous stores (warp = 16 rows, 32 lanes = 32 cols).
    bool colFull = (colBase + 128 <= NTOKEN);
    #pragma unroll 1
    for (int rr = 0; rr < 16; rr++) {
        int rl = wid * 16 + rr;
        int gr = rowBase + rl;
        if (gr >= NROWS) continue;               // warp-uniform
        size_t ob = (size_t)gr * NTOKEN + colBase;
        const float* srow = &stage[rl * OSTRIDE];
        if (colFull) {
            #pragma unroll
            for (int q = 0; q < 4; q++)
                out[ob + lane + q * 32] = srow[lane + q * 32];
        } else {
            #pragma unroll
            for (int q = 0; q < 4; q++) {
                int c = lane + q * 32;
                if (colBase + c < NTOKEN) out[ob + c] = srow[c];
            }
        }
    }

    // partial (m,s) combine + write
    if (tid < 128) {
        int gr = rowBase + tid;
        if (gr < NROWS) {
            float m0 = sm_m[0][tid], s0 = sm_s[0][tid];
            float m1 = sm_m[1][tid], s1 = sm_s[1][tid];
            float mm = fmaxf(m0, m1);
            float ssum = s0 * __expf(m0 - mm) + s1 * __expf(m1 - mm);
            g_pm[(size_t)gr * NTILES + blockIdx.x] = mm;
            g_ps[(size_t)gr * NTILES + blockIdx.x] = ssum;
        }
    }
}

// ---------------- launch 5: finalize lse + subtract (fused) ----------------
__global__ void k_subfin(float* __restrict__ out) {
    int row = blockIdx.x;
    const float* pm = &g_pm[(size_t)row * NTILES];
    const float* ps = &g_ps[(size_t)row * NTILES];
    float m = -1e30f, s = 0.f;
    for (int i = threadIdx.x; i < NTILES; i += blockDim.x) {
        float tm = pm[i], ts = ps[i];
        float nm = fmaxf(m, tm);
        s = s * __expf(m - nm) + ts * __expf(tm - nm);
        m = nm;
    }
    int lane = threadIdx.x & 31, w = threadIdx.x >> 5;
    #pragma unroll
    for (int o = 16; o; o >>= 1) {
        float om = __shfl_xor_sync(0xffffffffu, m, o);
        float os = __shfl_xor_sync(0xffffffffu, s, o);
        float nm = fmaxf(m, om);
        s = s * __expf(m - nm) + os * __expf(om - nm);
        m = nm;
    }
    __shared__ float shm[32], shs[32];
    __shared__ float sh_l;
    if (lane == 0) { shm[w] = m; shs[w] = s; }
    __syncthreads();
    if (threadIdx.x == 0) {
        int nw = (int)(blockDim.x >> 5);
        m = shm[0]; s = shs[0];
        for (int i = 1; i < nw; i++) {
            float nm = fmaxf(m, shm[i]);
            s = s * __expf(m - nm) + shs[i] * __expf(shm[i] - nm);
            m = nm;
        }
        sh_l = m + __logf(s);
    }
    __syncthreads();
    float l = sh_l;

    float* p = out + (size_t)row * NTOKEN;
    int head = (int)(((16u - ((uint32_t)(uintptr_t)p & 15u)) & 15u) >> 2);
    int n4 = (NTOKEN - head) >> 2;
    int tail = NTOKEN - head - n4 * 4;
    if (threadIdx.x < (unsigned)head) p[threadIdx.x] -= l;
    float4* p4 = (float4*)(p + head);
    for (int i = threadIdx.x; i < n4; i += blockDim.x) {
        float4 v = p4[i];
        v.x -= l; v.y -= l; v.z -= l; v.w -= l;
        p4[i] = v;
    }
    if (threadIdx.x < (unsigned)tail) p[head + n4 * 4 + threadIdx.x] -= l;
}

// ---------------- launch ----------------
extern "C" void kernel_launch(void* const* d_in, const int* in_sizes, int n_in,
                              void* d_out, int out_size) {
    const float* x     = (const float*)d_in[0];
    const float* dec_w = (const float*)d_in[1];
    const float* dec_b = (const float*)d_in[2];
    const float* enc_w = (const float*)d_in[3];
    const int*   tgt   = (const int*)d_in[4];
    float* out = (float*)d_out;

    k_pro_a<<<(unsigned)((XGRP + 255) / 256), 256>>>(x, tgt);            // 1
    k_pro_b<<<(unsigned)(WBLK + NROWS), 256>>>(dec_w, x, enc_w, tgt);    // 2
    k_noise<<<NROWS, 128>>>(x, tgt);                                     // 3
    cudaFuncSetAttribute(k_gemm_tc, cudaFuncAttributeMaxDynamicSharedMemorySize, SMEM_DYN);
    dim3 grid(NPAD / 128, MPAD / 128);
    k_gemm_tc<<<grid, 256, SMEM_DYN>>>(dec_b, tgt, out);                 // 4 (profiled)
    k_subfin<<<NROWS, 1024>>>(out);                                      // 5
}